// round 5
// baseline (speedup 1.0000x reference)
#include <cuda_runtime.h>
#include <stdint.h>

#define NN 40000
#define NE 640000
#define DD 128

// ---------------- packed-f32x2 helpers (SASS FFMA2 — ptxas never emits it) ---
#define FMA2(accv, a2, b2) \
    asm("fma.rn.f32x2 %0, %1, %2, %0;" : "+l"(accv) : "l"(a2), "l"(b2))
#define PACK2(dst, x) \
    asm("mov.b64 %0, {%1, %1};" : "=l"(dst) : "f"(x))
#define UNPACK2(lo, hi, v) \
    asm("mov.b64 {%0, %1}, %2;" : "=f"(lo), "=f"(hi) : "l"(v))

// ---------------- scratch (device globals; no runtime allocation) ------------
__device__ float g_agg[NN * DD];          // segment-sum of e onto dst
__device__ float g_deg[NN];               // in-degree (float)
__device__ float g_PQ[NN * 2 * DD];       // [n][0:128]=P=node@W1.T, [128:256]=Q=node@W2.T
__device__ float g_WeT[3 * DD * DD];      // W_e transposed: WeT[k][o] = W_e[o][k]
__device__ float g_WnT[2 * DD * DD];      // W_n transposed
__device__ int   g_src32[NE];             // normalized int32 indices
__device__ int   g_dst32[NE];

// ---------------- prep: zero accumulators + transpose weights ----------------
__global__ void k_prep(const float* __restrict__ We, const float* __restrict__ Wn) {
    const int NAGG = NN * DD;
    const int NWE = 3 * DD * DD;
    const int NWN = 2 * DD * DD;
    const int TOT = NAGG + NN + NWE + NWN;
    int stride = gridDim.x * blockDim.x;
    for (int idx = blockIdx.x * blockDim.x + threadIdx.x; idx < TOT; idx += stride) {
        if (idx < NAGG) {
            g_agg[idx] = 0.0f;
        } else if (idx < NAGG + NN) {
            g_deg[idx - NAGG] = 0.0f;
        } else if (idx < NAGG + NN + NWE) {
            int t = idx - NAGG - NN;
            int k = t >> 7, o = t & 127;
            g_WeT[t] = We[o * (3 * DD) + k];
        } else {
            int t = idx - NAGG - NN - NWE;
            int k = t >> 7, o = t & 127;
            g_WnT[t] = Wn[o * (2 * DD) + k];
        }
    }
}

// ---------------- index normalization: int64-or-int32 -> int32 + degree -----
// Reference declares src/dst int64, but JAX silently emits int32 unless x64 is
// enabled at dataset-gen time. Indices < 40000 << 2^32: for int64 data every
// odd 32-bit word is 0; for int32 data odd words are random indices.
__global__ void k_idx(const unsigned int* __restrict__ src_raw,
                      const unsigned int* __restrict__ dst_raw) {
    unsigned int probe = 0;
#pragma unroll
    for (int w = 0; w < 8; w++) probe |= src_raw[2 * w + 1] | dst_raw[2 * w + 1];
    bool is64 = (probe == 0);

    int stride = gridDim.x * blockDim.x;
    for (int i = blockIdx.x * blockDim.x + threadIdx.x; i < NE; i += stride) {
        int s, d;
        if (is64) {
            s = (int)src_raw[2 * i];   // little-endian low word of int64
            d = (int)dst_raw[2 * i];
        } else {
            s = (int)src_raw[i];
            d = (int)dst_raw[i];
        }
        g_src32[i] = s;
        g_dst32[i] = d;
        atomicAdd(&g_deg[d], 1.0f);
    }
}

// ---------------- common GEMM tile config ------------------------------------
// BM=128 rows, BN=128 cols, BK=16, 256 threads, 8x8 per-thread microtile,
// double-buffered SMEM (1 BAR per k-step; loads overlap FFMA2 compute).
#define BM 128
#define BN 128
#define BK 16
#define APAD 4   // row stride BK+4=20 floats -> 16B-aligned float4 stores

// Inner product step over one SMEM buffer: acc64[j][0..3] += {a,a}*Bpair
#define MICRO_KSTEP(As_, Bs_, acc64_)                                          \
    _Pragma("unroll")                                                          \
    for (int k = 0; k < BK; k++) {                                             \
        const unsigned long long* bp =                                         \
            (const unsigned long long*)&Bs_[k][tx * 8];                        \
        unsigned long long b0 = bp[0], b1 = bp[1], b2 = bp[2], b3 = bp[3];     \
        _Pragma("unroll")                                                      \
        for (int j = 0; j < 8; j++) {                                          \
            float a = As_[ty * 8 + j][k];                                      \
            unsigned long long aa;                                             \
            PACK2(aa, a);                                                      \
            FMA2(acc64_[j][0], aa, b0);                                        \
            FMA2(acc64_[j][1], aa, b1);                                        \
            FMA2(acc64_[j][2], aa, b2);                                        \
            FMA2(acc64_[j][3], aa, b3);                                        \
        }                                                                      \
    }

#define LOAD_A(As_, srcbase_, k0_)                                             \
    _Pragma("unroll")                                                          \
    for (int p = 0; p < 2; p++) {                                              \
        int idx = tid + p * 256;                                               \
        int m = idx >> 2;                                                      \
        int k4 = (idx & 3) << 2;                                               \
        int row = m0 + m; if (row >= NN) row = NN - 1;                         \
        float4 v = *(const float4*)((srcbase_) + (size_t)row * DD + (k0_) + k4);\
        *(float4*)&As_[m][k4] = v;                                             \
    }

#define LOAD_A_NOCLAMP(As_, srcbase_, k0_)                                     \
    _Pragma("unroll")                                                          \
    for (int p = 0; p < 2; p++) {                                              \
        int idx = tid + p * 256;                                               \
        int m = idx >> 2;                                                      \
        int k4 = (idx & 3) << 2;                                               \
        float4 v = *(const float4*)((srcbase_) + (size_t)(m0 + m) * DD + (k0_) + k4);\
        *(float4*)&As_[m][k4] = v;                                             \
    }

#define LOAD_B(Bs_, wbase_, k0_)                                               \
    _Pragma("unroll")                                                          \
    for (int p = 0; p < 2; p++) {                                              \
        int idx = tid + p * 256;                                               \
        int k = idx >> 5;                                                      \
        int o4 = (idx & 31) << 2;                                              \
        *(float4*)&Bs_[k][o4] =                                                \
            *(const float4*)((wbase_) + (size_t)((k0_) + k) * DD + o4);        \
    }

// ---------------- P/Q projection: [P|Q] = node_feats @ [W1|W2].T -------------
__global__ __launch_bounds__(256, 2)
void k_pq(const float* __restrict__ node_feats) {
    __shared__ float As[2][BM][BK + APAD];
    __shared__ float Bs[2][BK][BN];
    int tid = threadIdx.x;
    int tx = tid & 15, ty = tid >> 4;
    int m0 = blockIdx.x * BM;
    const float* Wbase = g_WeT + blockIdx.y * 128 * DD;

    unsigned long long acc64[8][4];
#pragma unroll
    for (int j = 0; j < 8; j++)
#pragma unroll
        for (int i = 0; i < 4; i++) acc64[j][i] = 0ULL;

    LOAD_A(As[0], node_feats, 0)
    LOAD_B(Bs[0], Wbase, 0)
    __syncthreads();

#pragma unroll
    for (int it = 0; it < 128 / BK; it++) {
        int cur = it & 1, nxt = cur ^ 1;
        int k0n = (it + 1) * BK;
        if (k0n < 128) {
            LOAD_A(As[nxt], node_feats, k0n)
            LOAD_B(Bs[nxt], Wbase, k0n)
        }
        MICRO_KSTEP(As[cur], Bs[cur], acc64)
        __syncthreads();
    }

    int half = blockIdx.y;
#pragma unroll
    for (int j = 0; j < 8; j++) {
        int row = m0 + ty * 8 + j;
        if (row < NN) {
            float r[8];
#pragma unroll
            for (int i = 0; i < 4; i++) UNPACK2(r[2 * i], r[2 * i + 1], acc64[j][i]);
            float* dstp = g_PQ + (size_t)row * 256 + half * 128 + tx * 8;
            *(float4*)dstp = make_float4(r[0], r[1], r[2], r[3]);
            *(float4*)(dstp + 4) = make_float4(r[4], r[5], r[6], r[7]);
        }
    }
}

// ---------------- edge kernel: e = ef@W3.T + P[src] + Q[dst] + b_e -----------
// Also: atomically accumulates e into g_agg[dst].
__global__ __launch_bounds__(256, 2)
void k_edge(const float* __restrict__ edge_feats,
            const float* __restrict__ b_e,
            float* __restrict__ e_out) {
    __shared__ float As[2][BM][BK + APAD];
    __shared__ float Bs[2][BK][BN];
    __shared__ int s_src[BM], s_dst[BM];

    int tid = threadIdx.x;
    int tx = tid & 15, ty = tid >> 4;
    int m0 = blockIdx.x * BM;

    if (tid < BM) {
        int e = m0 + tid;
        s_src[tid] = g_src32[e];
        s_dst[tid] = g_dst32[e];
    }

    unsigned long long acc64[8][4];
#pragma unroll
    for (int j = 0; j < 8; j++)
#pragma unroll
        for (int i = 0; i < 4; i++) acc64[j][i] = 0ULL;

    const float* Wbase = g_WeT + 256 * DD;  // W3 rows (k = 256..383)

    LOAD_A_NOCLAMP(As[0], edge_feats, 0)
    LOAD_B(Bs[0], Wbase, 0)
    __syncthreads();

#pragma unroll
    for (int it = 0; it < 128 / BK; it++) {
        int cur = it & 1, nxt = cur ^ 1;
        int k0n = (it + 1) * BK;
        if (k0n < 128) {
            LOAD_A_NOCLAMP(As[nxt], edge_feats, k0n)
            LOAD_B(Bs[nxt], Wbase, k0n)
        }
        MICRO_KSTEP(As[cur], Bs[cur], acc64)
        __syncthreads();
    }

    float4 be0 = *(const float4*)(b_e + tx * 8);
    float4 be1 = *(const float4*)(b_e + tx * 8 + 4);

    // ---- two-phase epilogue: batch ALL P/Q gathers before any asm RED ------
    // Phase 1: no volatile asm between the 32 LDG.128s -> compiler keeps them
    // in flight together (one ~L2 latency exposure instead of 8 serialized).
    float rr[8][8];
#pragma unroll
    for (int j = 0; j < 8; j++) {
        int m = ty * 8 + j;
        int sn = s_src[m], dn = s_dst[m];
        const float* Prow = g_PQ + (size_t)sn * 256 + tx * 8;
        const float* Qrow = g_PQ + (size_t)dn * 256 + 128 + tx * 8;
        float4 p0 = *(const float4*)Prow;
        float4 p1 = *(const float4*)(Prow + 4);
        float4 q0 = *(const float4*)Qrow;
        float4 q1 = *(const float4*)(Qrow + 4);
        float r[8];
#pragma unroll
        for (int i = 0; i < 4; i++) UNPACK2(r[2 * i], r[2 * i + 1], acc64[j][i]);
        rr[j][0] = r[0] + p0.x + q0.x + be0.x;
        rr[j][1] = r[1] + p0.y + q0.y + be0.y;
        rr[j][2] = r[2] + p0.z + q0.z + be0.z;
        rr[j][3] = r[3] + p0.w + q0.w + be0.w;
        rr[j][4] = r[4] + p1.x + q1.x + be1.x;
        rr[j][5] = r[5] + p1.y + q1.y + be1.y;
        rr[j][6] = r[6] + p1.z + q1.z + be1.z;
        rr[j][7] = r[7] + p1.w + q1.w + be1.w;
    }
    // Phase 2: all stores + REDs.
#pragma unroll
    for (int j = 0; j < 8; j++) {
        int m = ty * 8 + j;
        int eidx = m0 + m;
        int dn = s_dst[m];
        float4 r0 = make_float4(rr[j][0], rr[j][1], rr[j][2], rr[j][3]);
        float4 r1 = make_float4(rr[j][4], rr[j][5], rr[j][6], rr[j][7]);
        float* eo = e_out + (size_t)eidx * DD + tx * 8;
        *(float4*)eo = r0;
        *(float4*)(eo + 4) = r1;
        float* ag = g_agg + (size_t)dn * DD + tx * 8;
        asm volatile("red.global.add.v4.f32 [%0], {%1,%2,%3,%4};"
                     :: "l"(ag), "f"(r0.x), "f"(r0.y), "f"(r0.z), "f"(r0.w) : "memory");
        asm volatile("red.global.add.v4.f32 [%0], {%1,%2,%3,%4};"
                     :: "l"(ag + 4), "f"(r1.x), "f"(r1.y), "f"(r1.z), "f"(r1.w) : "memory");
    }
}

// ---------------- node kernel: n = [node | agg_mean] @ W_n.T + b_n ----------
__global__ __launch_bounds__(256, 2)
void k_node(const float* __restrict__ node_feats,
            const float* __restrict__ b_n,
            float* __restrict__ n_out) {
    __shared__ float As[2][BM][BK + APAD];
    __shared__ float Bs[2][BK][BN];
    __shared__ float s_inv[BM];

    int tid = threadIdx.x;
    int tx = tid & 15, ty = tid >> 4;
    int m0 = blockIdx.x * BM;

    if (tid < BM) {
        int row = m0 + tid;
        float dg = (row < NN) ? g_deg[row] : 0.0f;
        s_inv[tid] = (dg > 0.0f) ? (1.0f / dg) : 0.0f;
    }
    __syncthreads();

    unsigned long long acc64[8][4];
#pragma unroll
    for (int j = 0; j < 8; j++)
#pragma unroll
        for (int i = 0; i < 4; i++) acc64[j][i] = 0ULL;

    // A-tile loader for the concat [node | agg*inv_deg] matrix
#define LOAD_A_NODE(As_, k0_)                                                  \
    _Pragma("unroll")                                                          \
    for (int p = 0; p < 2; p++) {                                              \
        int idx = tid + p * 256;                                               \
        int m = idx >> 2;                                                      \
        int k4 = (idx & 3) << 2;                                               \
        int row = m0 + m; if (row >= NN) row = NN - 1;                         \
        float4 v;                                                              \
        if ((k0_) < 128) {                                                     \
            v = *(const float4*)(node_feats + (size_t)row * DD + (k0_) + k4);  \
        } else {                                                               \
            v = *(const float4*)(g_agg + (size_t)row * DD + ((k0_) - 128) + k4);\
            float s = s_inv[m];                                                \
            v.x *= s; v.y *= s; v.z *= s; v.w *= s;                            \
        }                                                                      \
        *(float4*)&As_[m][k4] = v;                                             \
    }

    LOAD_A_NODE(As[0], 0)
    LOAD_B(Bs[0], g_WnT, 0)
    __syncthreads();

#pragma unroll
    for (int it = 0; it < 256 / BK; it++) {
        int cur = it & 1, nxt = cur ^ 1;
        int k0n = (it + 1) * BK;
        if (k0n < 256) {
            LOAD_A_NODE(As[nxt], k0n)
            LOAD_B(Bs[nxt], g_WnT, k0n)
        }
        MICRO_KSTEP(As[cur], Bs[cur], acc64)
        __syncthreads();
    }

    float4 bn0 = *(const float4*)(b_n + tx * 8);
    float4 bn1 = *(const float4*)(b_n + tx * 8 + 4);
#pragma unroll
    for (int j = 0; j < 8; j++) {
        int row = m0 + ty * 8 + j;
        if (row < NN) {
            float r[8];
#pragma unroll
            for (int i = 0; i < 4; i++) UNPACK2(r[2 * i], r[2 * i + 1], acc64[j][i]);
            float4 r0 = make_float4(r[0] + bn0.x, r[1] + bn0.y,
                                    r[2] + bn0.z, r[3] + bn0.w);
            float4 r1 = make_float4(r[4] + bn1.x, r[5] + bn1.y,
                                    r[6] + bn1.z, r[7] + bn1.w);
            float* no = n_out + (size_t)row * DD + tx * 8;
            *(float4*)no = r0;
            *(float4*)(no + 4) = r1;
        }
    }
}

// ---------------- launch ------------------------------------------------------
extern "C" void kernel_launch(void* const* d_in, const int* in_sizes, int n_in,
                              void* d_out, int out_size) {
    const float* node_feats = (const float*)d_in[0];
    const float* edge_feats = (const float*)d_in[1];
    const unsigned int* src_raw = (const unsigned int*)d_in[2];
    const unsigned int* dst_raw = (const unsigned int*)d_in[3];
    const float* W_e        = (const float*)d_in[4];
    const float* b_e        = (const float*)d_in[5];
    const float* W_n        = (const float*)d_in[6];
    const float* b_n        = (const float*)d_in[7];

    float* out = (float*)d_out;
    float* n_out = out;                          // n: [40000, 128] first
    float* e_out = out + (size_t)NN * DD;        // e: [640000, 128] after

    // prep: zero agg/deg + transpose weights
    {
        int total = NN * DD + NN + 3 * DD * DD + 2 * DD * DD;
        int blocks = (total + 255) / 256;
        k_prep<<<blocks, 256>>>(W_e, W_n);
    }
    // index dtype normalization (+ degree count)
    k_idx<<<592, 256>>>(src_raw, dst_raw);
    // P|Q projections (needs g_WeT)
    k_pq<<<dim3((NN + BM - 1) / BM, 2), 256>>>(node_feats);
    // edge update + fused mean-aggregation accumulate
    k_edge<<<NE / BM, 256>>>(edge_feats, b_e, e_out);
    // node update
    k_node<<<(NN + BM - 1) / BM, 256>>>(node_feats, b_n, n_out);
}

// round 8
// speedup vs baseline: 1.0649x; 1.0649x over previous
#include <cuda_runtime.h>
#include <stdint.h>

#define NN 40000
#define NE 640000
#define DD 128

// ---------------- packed-f32x2 helpers (SASS FFMA2 — ptxas never emits it) ---
#define FMA2(accv, a2, b2) \
    asm("fma.rn.f32x2 %0, %1, %2, %0;" : "+l"(accv) : "l"(a2), "l"(b2))
#define PACK2(dst, x) \
    asm("mov.b64 %0, {%1, %1};" : "=l"(dst) : "f"(x))
#define UNPACK2(lo, hi, v) \
    asm("mov.b64 {%0, %1}, %2;" : "=f"(lo), "=f"(hi) : "l"(v))

// ---------------- scratch (device globals; no runtime allocation) ------------
__device__ float g_agg[NN * DD];          // segment-sum of e onto dst
__device__ float g_deg[NN];               // in-degree (float)
__device__ float g_PQ[NN * 2 * DD];       // [n][0:128]=P=node@W1.T, [128:256]=Q=node@W2.T
__device__ float g_WeT[3 * DD * DD];      // W_e transposed: WeT[k][o] = W_e[o][k]
__device__ float g_WnT[2 * DD * DD];      // W_n transposed
__device__ int   g_src32[NE];             // normalized int32 indices
__device__ int   g_dst32[NE];

// ---------------- prep: zero accumulators + transpose weights ----------------
__global__ void k_prep(const float* __restrict__ We, const float* __restrict__ Wn) {
    const int NAGG = NN * DD;
    const int NWE = 3 * DD * DD;
    const int NWN = 2 * DD * DD;
    const int TOT = NAGG + NN + NWE + NWN;
    int stride = gridDim.x * blockDim.x;
    for (int idx = blockIdx.x * blockDim.x + threadIdx.x; idx < TOT; idx += stride) {
        if (idx < NAGG) {
            g_agg[idx] = 0.0f;
        } else if (idx < NAGG + NN) {
            g_deg[idx - NAGG] = 0.0f;
        } else if (idx < NAGG + NN + NWE) {
            int t = idx - NAGG - NN;
            int k = t >> 7, o = t & 127;
            g_WeT[t] = We[o * (3 * DD) + k];
        } else {
            int t = idx - NAGG - NN - NWE;
            int k = t >> 7, o = t & 127;
            g_WnT[t] = Wn[o * (2 * DD) + k];
        }
    }
}

// ---------------- index normalization: int64-or-int32 -> int32 + degree -----
// Reference declares src/dst int64, but JAX silently emits int32 unless x64 is
// enabled at dataset-gen time. Indices < 40000 << 2^32: for int64 data every
// odd 32-bit word is 0; for int32 data odd words are random indices.
__global__ void k_idx(const unsigned int* __restrict__ src_raw,
                      const unsigned int* __restrict__ dst_raw) {
    unsigned int probe = 0;
#pragma unroll
    for (int w = 0; w < 8; w++) probe |= src_raw[2 * w + 1] | dst_raw[2 * w + 1];
    bool is64 = (probe == 0);

    int stride = gridDim.x * blockDim.x;
    for (int i = blockIdx.x * blockDim.x + threadIdx.x; i < NE; i += stride) {
        int s, d;
        if (is64) {
            s = (int)src_raw[2 * i];   // little-endian low word of int64
            d = (int)dst_raw[2 * i];
        } else {
            s = (int)src_raw[i];
            d = (int)dst_raw[i];
        }
        g_src32[i] = s;
        g_dst32[i] = d;
        atomicAdd(&g_deg[d], 1.0f);
    }
}

// ---------------- common GEMM tile config ------------------------------------
// BM=128 rows, BN=128 cols, BK=16, 256 threads, 8x8 per-thread microtile,
// double-buffered SMEM (1 BAR per k-step stage).
// B is stored PAIR-INTERLEAVED: Bs[k][i*16+tx] = float2(col tx*8+2i, tx*8+2i+1)
// so each B LDS.64 hits 16 lanes at 8B stride -> all 32 banks, conflict-free
// (R4 layout had 32B lane stride -> 4-way conflict -> L1 82% bound).
// A is read as LDS.64 over (k, k+1) pairs -> halves A wavefronts.
#define BM 128
#define BN 128
#define BK 16
#define APAD 4   // As row stride BK+4=20 floats -> 16B-aligned rows

// Inner product over one SMEM buffer, two k-steps at a time.
#define MICRO_KSTEP(As_, Bs_, acc64_)                                          \
    _Pragma("unroll")                                                          \
    for (int k = 0; k < BK; k += 2) {                                          \
        unsigned long long bk0[4], bk1[4];                                     \
        _Pragma("unroll")                                                      \
        for (int i = 0; i < 4; i++) {                                          \
            bk0[i] = *(const unsigned long long*)&Bs_[k][i * 16 + tx];         \
            bk1[i] = *(const unsigned long long*)&Bs_[k + 1][i * 16 + tx];     \
        }                                                                      \
        _Pragma("unroll")                                                      \
        for (int j = 0; j < 8; j++) {                                          \
            unsigned long long a2 =                                            \
                *(const unsigned long long*)&As_[ty * 8 + j][k];               \
            float alo, ahi;                                                    \
            UNPACK2(alo, ahi, a2);                                             \
            unsigned long long aa0, aa1;                                       \
            PACK2(aa0, alo);                                                   \
            PACK2(aa1, ahi);                                                   \
            FMA2(acc64_[j][0], aa0, bk0[0]);                                   \
            FMA2(acc64_[j][1], aa0, bk0[1]);                                   \
            FMA2(acc64_[j][2], aa0, bk0[2]);                                   \
            FMA2(acc64_[j][3], aa0, bk0[3]);                                   \
            FMA2(acc64_[j][0], aa1, bk1[0]);                                   \
            FMA2(acc64_[j][1], aa1, bk1[1]);                                   \
            FMA2(acc64_[j][2], aa1, bk1[2]);                                   \
            FMA2(acc64_[j][3], aa1, bk1[3]);                                   \
        }                                                                      \
    }

#define LOAD_A(As_, srcbase_, k0_)                                             \
    _Pragma("unroll")                                                          \
    for (int p = 0; p < 2; p++) {                                              \
        int idx = tid + p * 256;                                               \
        int m = idx >> 2;                                                      \
        int k4 = (idx & 3) << 2;                                               \
        int row = m0 + m; if (row >= NN) row = NN - 1;                         \
        float4 v = *(const float4*)((srcbase_) + (size_t)row * DD + (k0_) + k4);\
        *(float4*)&As_[m][k4] = v;                                             \
    }

#define LOAD_A_NOCLAMP(As_, srcbase_, k0_)                                     \
    _Pragma("unroll")                                                          \
    for (int p = 0; p < 2; p++) {                                              \
        int idx = tid + p * 256;                                               \
        int m = idx >> 2;                                                      \
        int k4 = (idx & 3) << 2;                                               \
        float4 v = *(const float4*)((srcbase_) + (size_t)(m0 + m) * DD + (k0_) + k4);\
        *(float4*)&As_[m][k4] = v;                                             \
    }

// Pair-interleaved B store: float4 (cols o4..o4+3) -> pairs i and i+1 at txb.
#define LOAD_B(Bs_, wbase_, k0_)                                               \
    _Pragma("unroll")                                                          \
    for (int p = 0; p < 2; p++) {                                              \
        int idx = tid + p * 256;                                               \
        int k = idx >> 5;                                                      \
        int o4 = (idx & 31) << 2;                                              \
        float4 v = *(const float4*)((wbase_) + (size_t)((k0_) + k) * DD + o4); \
        int i = (o4 & 7) >> 1;   /* 0 or 2 */                                  \
        int txb = o4 >> 3;                                                     \
        Bs_[k][i * 16 + txb] = make_float2(v.x, v.y);                          \
        Bs_[k][(i + 1) * 16 + txb] = make_float2(v.z, v.w);                    \
    }

// ---------------- P/Q projection: [P|Q] = node_feats @ [W1|W2].T -------------
__global__ __launch_bounds__(256, 2)
void k_pq(const float* __restrict__ node_feats) {
    __shared__ float As[2][BM][BK + APAD];
    __shared__ float2 Bs[2][BK][64];
    int tid = threadIdx.x;
    int tx = tid & 15, ty = tid >> 4;
    int m0 = blockIdx.x * BM;
    const float* Wbase = g_WeT + blockIdx.y * 128 * DD;

    unsigned long long acc64[8][4];
#pragma unroll
    for (int j = 0; j < 8; j++)
#pragma unroll
        for (int i = 0; i < 4; i++) acc64[j][i] = 0ULL;

    LOAD_A(As[0], node_feats, 0)
    LOAD_B(Bs[0], Wbase, 0)
    __syncthreads();

#pragma unroll
    for (int it = 0; it < 128 / BK; it++) {
        int cur = it & 1, nxt = cur ^ 1;
        int k0n = (it + 1) * BK;
        if (k0n < 128) {
            LOAD_A(As[nxt], node_feats, k0n)
            LOAD_B(Bs[nxt], Wbase, k0n)
        }
        MICRO_KSTEP(As[cur], Bs[cur], acc64)
        __syncthreads();
    }

    int half = blockIdx.y;
#pragma unroll
    for (int j = 0; j < 8; j++) {
        int row = m0 + ty * 8 + j;
        if (row < NN) {
            float r[8];
#pragma unroll
            for (int i = 0; i < 4; i++) UNPACK2(r[2 * i], r[2 * i + 1], acc64[j][i]);
            float* dstp = g_PQ + (size_t)row * 256 + half * 128 + tx * 8;
            *(float4*)dstp = make_float4(r[0], r[1], r[2], r[3]);
            *(float4*)(dstp + 4) = make_float4(r[4], r[5], r[6], r[7]);
        }
    }
}

// ---------------- edge kernel: e = ef@W3.T + P[src] + Q[dst] + b_e -----------
// Also: atomically accumulates e into g_agg[dst].
__global__ __launch_bounds__(256, 2)
void k_edge(const float* __restrict__ edge_feats,
            const float* __restrict__ b_e,
            float* __restrict__ e_out) {
    __shared__ float As[2][BM][BK + APAD];
    __shared__ float2 Bs[2][BK][64];
    __shared__ int s_src[BM], s_dst[BM];

    int tid = threadIdx.x;
    int tx = tid & 15, ty = tid >> 4;
    int m0 = blockIdx.x * BM;

    if (tid < BM) {
        int e = m0 + tid;
        s_src[tid] = g_src32[e];
        s_dst[tid] = g_dst32[e];
    }

    unsigned long long acc64[8][4];
#pragma unroll
    for (int j = 0; j < 8; j++)
#pragma unroll
        for (int i = 0; i < 4; i++) acc64[j][i] = 0ULL;

    const float* Wbase = g_WeT + 256 * DD;  // W3 rows (k = 256..383)

    LOAD_A_NOCLAMP(As[0], edge_feats, 0)
    LOAD_B(Bs[0], Wbase, 0)
    __syncthreads();

#pragma unroll
    for (int it = 0; it < 128 / BK; it++) {
        int cur = it & 1, nxt = cur ^ 1;
        int k0n = (it + 1) * BK;
        if (k0n < 128) {
            LOAD_A_NOCLAMP(As[nxt], edge_feats, k0n)
            LOAD_B(Bs[nxt], Wbase, k0n)
        }
        MICRO_KSTEP(As[cur], Bs[cur], acc64)
        __syncthreads();
    }

    float4 be0 = *(const float4*)(b_e + tx * 8);
    float4 be1 = *(const float4*)(b_e + tx * 8 + 4);

    // ---- two-phase epilogue: batch ALL P/Q gathers before any asm RED ------
    float rr[8][8];
#pragma unroll
    for (int j = 0; j < 8; j++) {
        int m = ty * 8 + j;
        int sn = s_src[m], dn = s_dst[m];
        const float* Prow = g_PQ + (size_t)sn * 256 + tx * 8;
        const float* Qrow = g_PQ + (size_t)dn * 256 + 128 + tx * 8;
        float4 p0 = *(const float4*)Prow;
        float4 p1 = *(const float4*)(Prow + 4);
        float4 q0 = *(const float4*)Qrow;
        float4 q1 = *(const float4*)(Qrow + 4);
        float r[8];
#pragma unroll
        for (int i = 0; i < 4; i++) UNPACK2(r[2 * i], r[2 * i + 1], acc64[j][i]);
        rr[j][0] = r[0] + p0.x + q0.x + be0.x;
        rr[j][1] = r[1] + p0.y + q0.y + be0.y;
        rr[j][2] = r[2] + p0.z + q0.z + be0.z;
        rr[j][3] = r[3] + p0.w + q0.w + be0.w;
        rr[j][4] = r[4] + p1.x + q1.x + be1.x;
        rr[j][5] = r[5] + p1.y + q1.y + be1.y;
        rr[j][6] = r[6] + p1.z + q1.z + be1.z;
        rr[j][7] = r[7] + p1.w + q1.w + be1.w;
    }
#pragma unroll
    for (int j = 0; j < 8; j++) {
        int m = ty * 8 + j;
        int eidx = m0 + m;
        int dn = s_dst[m];
        float4 r0 = make_float4(rr[j][0], rr[j][1], rr[j][2], rr[j][3]);
        float4 r1 = make_float4(rr[j][4], rr[j][5], rr[j][6], rr[j][7]);
        float* eo = e_out + (size_t)eidx * DD + tx * 8;
        *(float4*)eo = r0;
        *(float4*)(eo + 4) = r1;
        float* ag = g_agg + (size_t)dn * DD + tx * 8;
        asm volatile("red.global.add.v4.f32 [%0], {%1,%2,%3,%4};"
                     :: "l"(ag), "f"(r0.x), "f"(r0.y), "f"(r0.z), "f"(r0.w) : "memory");
        asm volatile("red.global.add.v4.f32 [%0], {%1,%2,%3,%4};"
                     :: "l"(ag + 4), "f"(r1.x), "f"(r1.y), "f"(r1.z), "f"(r1.w) : "memory");
    }
}

// ---------------- node kernel: n = [node | agg_mean] @ W_n.T + b_n ----------
__global__ __launch_bounds__(256, 2)
void k_node(const float* __restrict__ node_feats,
            const float* __restrict__ b_n,
            float* __restrict__ n_out) {
    __shared__ float As[2][BM][BK + APAD];
    __shared__ float2 Bs[2][BK][64];
    __shared__ float s_inv[BM];

    int tid = threadIdx.x;
    int tx = tid & 15, ty = tid >> 4;
    int m0 = blockIdx.x * BM;

    if (tid < BM) {
        int row = m0 + tid;
        float dg = (row < NN) ? g_deg[row] : 0.0f;
        s_inv[tid] = (dg > 0.0f) ? (1.0f / dg) : 0.0f;
    }
    __syncthreads();

    unsigned long long acc64[8][4];
#pragma unroll
    for (int j = 0; j < 8; j++)
#pragma unroll
        for (int i = 0; i < 4; i++) acc64[j][i] = 0ULL;

    // A-tile loader for the concat [node | agg*inv_deg] matrix
#define LOAD_A_NODE(As_, k0_)                                                  \
    _Pragma("unroll")                                                          \
    for (int p = 0; p < 2; p++) {                                              \
        int idx = tid + p * 256;                                               \
        int m = idx >> 2;                                                      \
        int k4 = (idx & 3) << 2;                                               \
        int row = m0 + m; if (row >= NN) row = NN - 1;                         \
        float4 v;                                                              \
        if ((k0_) < 128) {                                                     \
            v = *(const float4*)(node_feats + (size_t)row * DD + (k0_) + k4);  \
        } else {                                                               \
            v = *(const float4*)(g_agg + (size_t)row * DD + ((k0_) - 128) + k4);\
            float s = s_inv[m];                                                \
            v.x *= s; v.y *= s; v.z *= s; v.w *= s;                            \
        }                                                                      \
        *(float4*)&As_[m][k4] = v;                                             \
    }

    LOAD_A_NODE(As[0], 0)
    LOAD_B(Bs[0], g_WnT, 0)
    __syncthreads();

#pragma unroll
    for (int it = 0; it < 256 / BK; it++) {
        int cur = it & 1, nxt = cur ^ 1;
        int k0n = (it + 1) * BK;
        if (k0n < 256) {
            LOAD_A_NODE(As[nxt], k0n)
            LOAD_B(Bs[nxt], g_WnT, k0n)
        }
        MICRO_KSTEP(As[cur], Bs[cur], acc64)
        __syncthreads();
    }

    float4 bn0 = *(const float4*)(b_n + tx * 8);
    float4 bn1 = *(const float4*)(b_n + tx * 8 + 4);
#pragma unroll
    for (int j = 0; j < 8; j++) {
        int row = m0 + ty * 8 + j;
        if (row < NN) {
            float r[8];
#pragma unroll
            for (int i = 0; i < 4; i++) UNPACK2(r[2 * i], r[2 * i + 1], acc64[j][i]);
            float4 r0 = make_float4(r[0] + bn0.x, r[1] + bn0.y,
                                    r[2] + bn0.z, r[3] + bn0.w);
            float4 r1 = make_float4(r[4] + bn1.x, r[5] + bn1.y,
                                    r[6] + bn1.z, r[7] + bn1.w);
            float* no = n_out + (size_t)row * DD + tx * 8;
            *(float4*)no = r0;
            *(float4*)(no + 4) = r1;
        }
    }
}

// ---------------- launch ------------------------------------------------------
extern "C" void kernel_launch(void* const* d_in, const int* in_sizes, int n_in,
                              void* d_out, int out_size) {
    const float* node_feats = (const float*)d_in[0];
    const float* edge_feats = (const float*)d_in[1];
    const unsigned int* src_raw = (const unsigned int*)d_in[2];
    const unsigned int* dst_raw = (const unsigned int*)d_in[3];
    const float* W_e        = (const float*)d_in[4];
    const float* b_e        = (const float*)d_in[5];
    const float* W_n        = (const float*)d_in[6];
    const float* b_n        = (const float*)d_in[7];

    float* out = (float*)d_out;
    float* n_out = out;                          // n: [40000, 128] first
    float* e_out = out + (size_t)NN * DD;        // e: [640000, 128] after

    // prep: zero agg/deg + transpose weights
    {
        int total = NN * DD + NN + 3 * DD * DD + 2 * DD * DD;
        int blocks = (total + 255) / 256;
        k_prep<<<blocks, 256>>>(W_e, W_n);
    }
    // index dtype normalization (+ degree count)
    k_idx<<<592, 256>>>(src_raw, dst_raw);
    // P|Q projections (needs g_WeT)
    k_pq<<<dim3((NN + BM - 1) / BM, 2), 256>>>(node_feats);
    // edge update + fused mean-aggregation accumulate
    k_edge<<<NE / BM, 256>>>(edge_feats, b_e, e_out);
    // node update
    k_node<<<(NN + BM - 1) / BM, 256>>>(node_feats, b_n, n_out);
}

// round 14
// speedup vs baseline: 1.0888x; 1.0224x over previous
#include <cuda_runtime.h>
#include <stdint.h>

#define NN 40000
#define NE 640000
#define DD 128

// ---------------- packed-f32x2 helpers (SASS FFMA2 — ptxas never emits it) ---
#define FMA2(accv, a2, b2) \
    asm("fma.rn.f32x2 %0, %1, %2, %0;" : "+l"(accv) : "l"(a2), "l"(b2))
#define PACK2(dst, x) \
    asm("mov.b64 %0, {%1, %1};" : "=l"(dst) : "f"(x))
#define UNPACK2(lo, hi, v) \
    asm("mov.b64 {%0, %1}, %2;" : "=f"(lo), "=f"(hi) : "l"(v))

// ---------------- cp.async (LDGSTS) helpers ----------------------------------
__device__ __forceinline__ unsigned smem_u32(const void* p) {
    return (unsigned)__cvta_generic_to_shared(p);
}
#define CPA16(dst, src) \
    asm volatile("cp.async.cg.shared.global [%0], [%1], 16;" :: "r"(dst), "l"(src))
#define CPA8(dst, src) \
    asm volatile("cp.async.ca.shared.global [%0], [%1], 8;"  :: "r"(dst), "l"(src))
#define CP_COMMIT()   asm volatile("cp.async.commit_group;" ::: "memory")
#define CP_WAIT_ALL() asm volatile("cp.async.wait_group 0;" ::: "memory")

// ---------------- scratch (device globals; no runtime allocation) ------------
__device__ float g_agg[NN * DD];          // segment-sum of e onto dst (then mean)
__device__ float g_deg[NN];               // in-degree (float)
__device__ float g_PQ[NN * 2 * DD];       // [n][0:128]=P=node@W1.T, [128:256]=Q=node@W2.T
__device__ float g_WeT[3 * DD * DD];      // W_e transposed: WeT[k][o] = W_e[o][k]
__device__ float g_WnT[2 * DD * DD];      // W_n transposed
__device__ int   g_src32[NE];             // normalized int32 indices
__device__ int   g_dst32[NE];

// ---------------- prep: zero accumulators + transpose weights ----------------
__global__ void k_prep(const float* __restrict__ We, const float* __restrict__ Wn) {
    const int NAGG = NN * DD;
    const int NWE = 3 * DD * DD;
    const int NWN = 2 * DD * DD;
    const int TOT = NAGG + NN + NWE + NWN;
    int stride = gridDim.x * blockDim.x;
    for (int idx = blockIdx.x * blockDim.x + threadIdx.x; idx < TOT; idx += stride) {
        if (idx < NAGG) {
            g_agg[idx] = 0.0f;
        } else if (idx < NAGG + NN) {
            g_deg[idx - NAGG] = 0.0f;
        } else if (idx < NAGG + NN + NWE) {
            int t = idx - NAGG - NN;
            int k = t >> 7, o = t & 127;
            g_WeT[t] = We[o * (3 * DD) + k];
        } else {
            int t = idx - NAGG - NN - NWE;
            int k = t >> 7, o = t & 127;
            g_WnT[t] = Wn[o * (2 * DD) + k];
        }
    }
}

// ---------------- index normalization: int64-or-int32 -> int32 + degree -----
__global__ void k_idx(const unsigned int* __restrict__ src_raw,
                      const unsigned int* __restrict__ dst_raw) {
    unsigned int probe = 0;
#pragma unroll
    for (int w = 0; w < 8; w++) probe |= src_raw[2 * w + 1] | dst_raw[2 * w + 1];
    bool is64 = (probe == 0);

    int stride = gridDim.x * blockDim.x;
    for (int i = blockIdx.x * blockDim.x + threadIdx.x; i < NE; i += stride) {
        int s, d;
        if (is64) {
            s = (int)src_raw[2 * i];   // little-endian low word of int64
            d = (int)dst_raw[2 * i];
        } else {
            s = (int)src_raw[i];
            d = (int)dst_raw[i];
        }
        g_src32[i] = s;
        g_dst32[i] = d;
        atomicAdd(&g_deg[d], 1.0f);
    }
}

// ---------------- agg -> mean: g_agg /= deg (0 if deg==0) --------------------
// Pulled out of k_node so its A-loader is a pure copy (cp.async-able).
__global__ void k_scale() {
    int i = blockIdx.x * blockDim.x + threadIdx.x;
    if (i < NN * DD) {
        float dg = g_deg[i >> 7];
        float v = g_agg[i];
        g_agg[i] = (dg > 0.0f) ? v / dg : 0.0f;
    }
}

// ---------------- common GEMM tile config ------------------------------------
// BM=128, BN=128, BK=16, 256 threads, 8x8 microtile. Double-buffered SMEM fed
// by cp.async (no LDG->reg->STS staging), ONE barrier per stage:
//   prologue: cp.async stage0, commit
//   iter it : wait_group 0; __syncthreads(); [cp.async stage it+1, commit];
//             compute stage it   (stage it+1 loads overlap this compute)
// WAR-safe: the barrier orders iteration it-1's compute before the overwrite
// of its buffer by iteration it's cp.async issue.
// B pair-interleaved: Bs[k][i*16+txb] = cols txb*8+2i, +2i+1 (conflict-free
// LDS.64 reads). Built via 8-byte cp.asyncs straight from GMEM.
#define BM 128
#define BN 128
#define BK 16
#define APAD 4   // As row stride 20 floats = 80B -> every (m,k4) dst 16B-aligned

// Inner product over one SMEM buffer, two k-steps at a time.
#define MICRO_KSTEP(As_, Bs_, acc64_)                                          \
    _Pragma("unroll")                                                          \
    for (int k = 0; k < BK; k += 2) {                                          \
        unsigned long long bk0[4], bk1[4];                                     \
        _Pragma("unroll")                                                      \
        for (int i = 0; i < 4; i++) {                                          \
            bk0[i] = *(const unsigned long long*)&Bs_[k][i * 16 + tx];         \
            bk1[i] = *(const unsigned long long*)&Bs_[k + 1][i * 16 + tx];     \
        }                                                                      \
        _Pragma("unroll")                                                      \
        for (int j = 0; j < 8; j++) {                                          \
            unsigned long long a2 =                                            \
                *(const unsigned long long*)&As_[ty * 8 + j][k];               \
            float alo, ahi;                                                    \
            UNPACK2(alo, ahi, a2);                                             \
            unsigned long long aa0, aa1;                                       \
            PACK2(aa0, alo);                                                   \
            PACK2(aa1, ahi);                                                   \
            FMA2(acc64_[j][0], aa0, bk0[0]);                                   \
            FMA2(acc64_[j][1], aa0, bk0[1]);                                   \
            FMA2(acc64_[j][2], aa0, bk0[2]);                                   \
            FMA2(acc64_[j][3], aa0, bk0[3]);                                   \
            FMA2(acc64_[j][0], aa1, bk1[0]);                                   \
            FMA2(acc64_[j][1], aa1, bk1[1]);                                   \
            FMA2(acc64_[j][2], aa1, bk1[2]);                                   \
            FMA2(acc64_[j][3], aa1, bk1[3]);                                   \
        }                                                                      \
    }

// A tile: 2x 16B cp.async per thread.
#define CP_A(As_, srcbase_, k0_)                                               \
    _Pragma("unroll")                                                          \
    for (int p = 0; p < 2; p++) {                                              \
        int idx = tid + p * 256;                                               \
        int m = idx >> 2;                                                      \
        int k4 = (idx & 3) << 2;                                               \
        CPA16(smem_u32(&As_[m][k4]),                                           \
              (srcbase_) + (size_t)(m0 + m) * DD + (k0_) + k4);                \
    }

#define CP_A_CLAMP(As_, srcbase_, k0_)                                         \
    _Pragma("unroll")                                                          \
    for (int p = 0; p < 2; p++) {                                              \
        int idx = tid + p * 256;                                               \
        int m = idx >> 2;                                                      \
        int k4 = (idx & 3) << 2;                                               \
        int row = m0 + m; if (row >= NN) row = NN - 1;                         \
        CPA16(smem_u32(&As_[m][k4]),                                           \
              (srcbase_) + (size_t)row * DD + (k0_) + k4);                     \
    }

// B tile: 4x 8B cp.async per thread; pair c2 -> slot (c2&3)*16 + (c2>>2).
// Lanes consecutive in c2 -> contiguous GMEM.
#define CP_B(Bs_, wbase_, k0_)                                                 \
    _Pragma("unroll")                                                          \
    for (int p = 0; p < 4; p++) {                                              \
        int idx = tid + p * 256;                                               \
        int k = idx >> 6;                                                      \
        int c2 = idx & 63;                                                     \
        CPA8(smem_u32(&Bs_[k][(c2 & 3) * 16 + (c2 >> 2)]),                     \
             (wbase_) + (size_t)((k0_) + k) * DD + c2 * 2);                    \
    }

// ---------------- P/Q projection: [P|Q] = node_feats @ [W1|W2].T -------------
__global__ __launch_bounds__(256, 2)
void k_pq(const float* __restrict__ node_feats) {
    __shared__ float As[2][BM][BK + APAD];
    __shared__ float2 Bs[2][BK][64];
    int tid = threadIdx.x;
    int tx = tid & 15, ty = tid >> 4;
    int m0 = blockIdx.x * BM;
    const float* Wbase = g_WeT + blockIdx.y * 128 * DD;

    unsigned long long acc64[8][4];
#pragma unroll
    for (int j = 0; j < 8; j++)
#pragma unroll
        for (int i = 0; i < 4; i++) acc64[j][i] = 0ULL;

    CP_A_CLAMP(As[0], node_feats, 0)
    CP_B(Bs[0], Wbase, 0)
    CP_COMMIT();

#pragma unroll
    for (int it = 0; it < 128 / BK; it++) {
        int cur = it & 1, nxt = cur ^ 1;
        int k0n = (it + 1) * BK;
        CP_WAIT_ALL();
        __syncthreads();
        if (k0n < 128) {
            CP_A_CLAMP(As[nxt], node_feats, k0n)
            CP_B(Bs[nxt], Wbase, k0n)
            CP_COMMIT();
        }
        MICRO_KSTEP(As[cur], Bs[cur], acc64)
    }

    int half = blockIdx.y;
#pragma unroll
    for (int j = 0; j < 8; j++) {
        int row = m0 + ty * 8 + j;
        if (row < NN) {
            float r[8];
#pragma unroll
            for (int i = 0; i < 4; i++) UNPACK2(r[2 * i], r[2 * i + 1], acc64[j][i]);
            float* dstp = g_PQ + (size_t)row * 256 + half * 128 + tx * 8;
            *(float4*)dstp = make_float4(r[0], r[1], r[2], r[3]);
            *(float4*)(dstp + 4) = make_float4(r[4], r[5], r[6], r[7]);
        }
    }
}

// ---------------- edge kernel: e = ef@W3.T + P[src] + Q[dst] + b_e -----------
// Also: atomically accumulates e into g_agg[dst].
__global__ __launch_bounds__(256, 2)
void k_edge(const float* __restrict__ edge_feats,
            const float* __restrict__ b_e,
            float* __restrict__ e_out) {
    __shared__ float As[2][BM][BK + APAD];
    __shared__ float2 Bs[2][BK][64];
    __shared__ int s_src[BM], s_dst[BM];

    int tid = threadIdx.x;
    int tx = tid & 15, ty = tid >> 4;
    int m0 = blockIdx.x * BM;

    if (tid < BM) {
        int e = m0 + tid;
        s_src[tid] = g_src32[e];
        s_dst[tid] = g_dst32[e];
    }

    unsigned long long acc64[8][4];
#pragma unroll
    for (int j = 0; j < 8; j++)
#pragma unroll
        for (int i = 0; i < 4; i++) acc64[j][i] = 0ULL;

    const float* Wbase = g_WeT + 256 * DD;  // W3 rows (k = 256..383)

    CP_A(As[0], edge_feats, 0)
    CP_B(Bs[0], Wbase, 0)
    CP_COMMIT();

#pragma unroll
    for (int it = 0; it < 128 / BK; it++) {
        int cur = it & 1, nxt = cur ^ 1;
        int k0n = (it + 1) * BK;
        CP_WAIT_ALL();
        __syncthreads();
        if (k0n < 128) {
            CP_A(As[nxt], edge_feats, k0n)
            CP_B(Bs[nxt], Wbase, k0n)
            CP_COMMIT();
        }
        MICRO_KSTEP(As[cur], Bs[cur], acc64)
    }

    float4 be0 = *(const float4*)(b_e + tx * 8);
    float4 be1 = *(const float4*)(b_e + tx * 8 + 4);

    // ---- two-phase epilogue: batch ALL P/Q gathers before any asm RED ------
    float rr[8][8];
#pragma unroll
    for (int j = 0; j < 8; j++) {
        int m = ty * 8 + j;
        int sn = s_src[m], dn = s_dst[m];
        const float* Prow = g_PQ + (size_t)sn * 256 + tx * 8;
        const float* Qrow = g_PQ + (size_t)dn * 256 + 128 + tx * 8;
        float4 p0 = *(const float4*)Prow;
        float4 p1 = *(const float4*)(Prow + 4);
        float4 q0 = *(const float4*)Qrow;
        float4 q1 = *(const float4*)(Qrow + 4);
        float r[8];
#pragma unroll
        for (int i = 0; i < 4; i++) UNPACK2(r[2 * i], r[2 * i + 1], acc64[j][i]);
        rr[j][0] = r[0] + p0.x + q0.x + be0.x;
        rr[j][1] = r[1] + p0.y + q0.y + be0.y;
        rr[j][2] = r[2] + p0.z + q0.z + be0.z;
        rr[j][3] = r[3] + p0.w + q0.w + be0.w;
        rr[j][4] = r[4] + p1.x + q1.x + be1.x;
        rr[j][5] = r[5] + p1.y + q1.y + be1.y;
        rr[j][6] = r[6] + p1.z + q1.z + be1.z;
        rr[j][7] = r[7] + p1.w + q1.w + be1.w;
    }
#pragma unroll
    for (int j = 0; j < 8; j++) {
        int m = ty * 8 + j;
        int eidx = m0 + m;
        int dn = s_dst[m];
        float4 r0 = make_float4(rr[j][0], rr[j][1], rr[j][2], rr[j][3]);
        float4 r1 = make_float4(rr[j][4], rr[j][5], rr[j][6], rr[j][7]);
        float* eo = e_out + (size_t)eidx * DD + tx * 8;
        *(float4*)eo = r0;
        *(float4*)(eo + 4) = r1;
        float* ag = g_agg + (size_t)dn * DD + tx * 8;
        asm volatile("red.global.add.v4.f32 [%0], {%1,%2,%3,%4};"
                     :: "l"(ag), "f"(r0.x), "f"(r0.y), "f"(r0.z), "f"(r0.w) : "memory");
        asm volatile("red.global.add.v4.f32 [%0], {%1,%2,%3,%4};"
                     :: "l"(ag + 4), "f"(r1.x), "f"(r1.y), "f"(r1.z), "f"(r1.w) : "memory");
    }
}

// ---------------- node kernel: n = [node | agg_mean] @ W_n.T + b_n ----------
// g_agg already holds the mean (k_scale ran) -> pure-copy A loader.
__global__ __launch_bounds__(256, 2)
void k_node(const float* __restrict__ node_feats,
            const float* __restrict__ b_n,
            float* __restrict__ n_out) {
    __shared__ float As[2][BM][BK + APAD];
    __shared__ float2 Bs[2][BK][64];

    int tid = threadIdx.x;
    int tx = tid & 15, ty = tid >> 4;
    int m0 = blockIdx.x * BM;

    unsigned long long acc64[8][4];
#pragma unroll
    for (int j = 0; j < 8; j++)
#pragma unroll
        for (int i = 0; i < 4; i++) acc64[j][i] = 0ULL;

#define CP_A_NODE(As_, k0_)                                                    \
    _Pragma("unroll")                                                          \
    for (int p = 0; p < 2; p++) {                                              \
        int idx = tid + p * 256;                                               \
        int m = idx >> 2;                                                      \
        int k4 = (idx & 3) << 2;                                               \
        int row = m0 + m; if (row >= NN) row = NN - 1;                         \
        const float* sp = ((k0_) < 128)                                        \
            ? node_feats + (size_t)row * DD + (k0_) + k4                       \
            : g_agg + (size_t)row * DD + ((k0_) - 128) + k4;                   \
        CPA16(smem_u32(&As_[m][k4]), sp);                                      \
    }

    CP_A_NODE(As[0], 0)
    CP_B(Bs[0], g_WnT, 0)
    CP_COMMIT();

#pragma unroll
    for (int it = 0; it < 256 / BK; it++) {
        int cur = it & 1, nxt = cur ^ 1;
        int k0n = (it + 1) * BK;
        CP_WAIT_ALL();
        __syncthreads();
        if (k0n < 256) {
            CP_A_NODE(As[nxt], k0n)
            CP_B(Bs[nxt], g_WnT, k0n)
            CP_COMMIT();
        }
        MICRO_KSTEP(As[cur], Bs[cur], acc64)
    }

    float4 bn0 = *(const float4*)(b_n + tx * 8);
    float4 bn1 = *(const float4*)(b_n + tx * 8 + 4);
#pragma unroll
    for (int j = 0; j < 8; j++) {
        int row = m0 + ty * 8 + j;
        if (row < NN) {
            float r[8];
#pragma unroll
            for (int i = 0; i < 4; i++) UNPACK2(r[2 * i], r[2 * i + 1], acc64[j][i]);
            float4 r0 = make_float4(r[0] + bn0.x, r[1] + bn0.y,
                                    r[2] + bn0.z, r[3] + bn0.w);
            float4 r1 = make_float4(r[4] + bn1.x, r[5] + bn1.y,
                                    r[6] + bn1.z, r[7] + bn1.w);
            float* no = n_out + (size_t)row * DD + tx * 8;
            *(float4*)no = r0;
            *(float4*)(no + 4) = r1;
        }
    }
}

// ---------------- launch ------------------------------------------------------
extern "C" void kernel_launch(void* const* d_in, const int* in_sizes, int n_in,
                              void* d_out, int out_size) {
    const float* node_feats = (const float*)d_in[0];
    const float* edge_feats = (const float*)d_in[1];
    const unsigned int* src_raw = (const unsigned int*)d_in[2];
    const unsigned int* dst_raw = (const unsigned int*)d_in[3];
    const float* W_e        = (const float*)d_in[4];
    const float* b_e        = (const float*)d_in[5];
    const float* W_n        = (const float*)d_in[6];
    const float* b_n        = (const float*)d_in[7];

    float* out = (float*)d_out;
    float* n_out = out;                          // n: [40000, 128] first
    float* e_out = out + (size_t)NN * DD;        // e: [640000, 128] after

    // prep: zero agg/deg + transpose weights
    {
        int total = NN * DD + NN + 3 * DD * DD + 2 * DD * DD;
        int blocks = (total + 255) / 256;
        k_prep<<<blocks, 256>>>(W_e, W_n);
    }
    // index dtype normalization (+ degree count)
    k_idx<<<592, 256>>>(src_raw, dst_raw);
    // P|Q projections (needs g_WeT)
    k_pq<<<dim3((NN + BM - 1) / BM, 2), 256>>>(node_feats);
    // edge update + fused mean-aggregation accumulate
    k_edge<<<NE / BM, 256>>>(edge_feats, b_e, e_out);
    // agg -> mean
    k_scale<<<(NN * DD + 255) / 256, 256>>>();
    // node update
    k_node<<<(NN + BM - 1) / BM, 256>>>(node_feats, b_n, n_out);
}